// round 13
// baseline (speedup 1.0000x reference)
#include <cuda_runtime.h>
#include <cstdint>

#define B_     8
#define S_     2048
#define N_     4096
#define D_     256
#define SLOTS  (D_ / 4)      // 64 float4 per row
#define BLK    16            // >= max span extent (width <= 15 -> <= 16 rows)
#define NBLK   (S_ / BLK)    // 128

#define PREP_CTAS 256        // 256 CTAs x 256 thr = 65536 prep threads
#define SPAN_CTAS ((B_ * N_) / 8)   // 4096 (warp per span, 8 spans/CTA)

// Scratch (fp32): block-local inclusive prefix P (16.8 MB) + block totals T (1 MB).
// Span sum over rows [low, end]:
//   sum = P[end] + (cross ? T[blkE-1] : 0) - (haveSub ? P[low-1] : 0)
// cross = blk(low) != blk(end); cross => haveSub (width <= 15).
__device__ float g_P[(size_t)B_ * S_ * D_];
__device__ float g_T[(size_t)B_ * NBLK * D_];

// Software grid barrier state (reset by last span CTA -> graph-replay safe).
__device__ int g_done = 0;   // prep CTAs completed
__device__ int g_fin  = 0;   // span CTAs completed

__global__ __launch_bounds__(256) void fused_kernel(
    const float4* __restrict__ seq4,    // [B, S, D/4]
    const int2*   __restrict__ spans,   // [B, N]
    float4*       __restrict__ out4)    // [B, N, D/4]
{
    const int cta = blockIdx.x;

    if (cta < PREP_CTAS) {
        // ── prep role: streaming block-local prefix + total ──────────────────
        const int t    = cta * 256 + threadIdx.x;     // 0 .. 65535
        const int slot = t & (SLOTS - 1);
        const int p    = t >> 6;                      // (b, blk)
        const int blk  = p & (NBLK - 1);
        const int b    = p >> 7;                      // NBLK = 128

        const size_t base = ((size_t)b * S_ + (size_t)blk * BLK) * SLOTS + slot;
        const float4* __restrict__ q  = seq4 + base;
        float4* __restrict__        Pp = reinterpret_cast<float4*>(g_P) + base;

        float4 s = make_float4(0.f, 0.f, 0.f, 0.f);
#pragma unroll
        for (int r = 0; r < BLK; ++r) {
            const float4 v = __ldg(q + r * SLOTS);    // input is truly read-only
            s.x += v.x; s.y += v.y; s.z += v.z; s.w += v.w;
            Pp[r * SLOTS] = s;
        }
        reinterpret_cast<float4*>(g_T)[((size_t)b * NBLK + blk) * SLOTS + slot] = s;

        __syncthreads();
        if (threadIdx.x == 0) {
            __threadfence();                           // release P/T stores
            atomicAdd(&g_done, 1);
        }
        return;
    }

    // ── span role: metadata + addressing BEFORE the barrier (overlaps prep) ──
    const int span = (cta - PREP_CTAS) * 8 + (threadIdx.x >> 5);
    const int lane = threadIdx.x & 31;
    const int b    = span >> 12;                 // N_ = 4096

    const int2 se  = __ldg(&spans[span]);
    const int end  = se.y;
    const int m    = min(end - se.x, end);       // mask(w) <=> w <= m
    const int low  = end - m;                    // rows [low, end], count m+1

    const bool haveSub = (low & (BLK - 1)) != 0;
    const bool cross   = (low >> 4) != (end >> 4);   // => haveSub, blkE >= 1
    const int  selRow  = max(low - 1, 0);

    const float4* hiP = reinterpret_cast<const float4*>(g_P)
                      + (size_t)b * S_ * SLOTS + (size_t)end    * SLOTS + lane;
    const float4* sbP = reinterpret_cast<const float4*>(g_P)
                      + (size_t)b * S_ * SLOTS + (size_t)selRow * SLOTS + lane;
    const float4* tP  = reinterpret_cast<const float4*>(g_T)
                      + ((size_t)b * NBLK + max((end >> 4) - 1, 0)) * SLOTS + lane;

    const float inv = 1.0f / fmaxf((float)(m + 1), 1e-13f);
    const float fs  = haveSub ? inv : 0.0f;

    // ── barrier: wait for all prep CTAs (acquire) ────────────────────────────
    if (threadIdx.x == 0) {
        int v;
        do {
            asm volatile("ld.global.acquire.gpu.b32 %0, [%1];"
                         : "=r"(v) : "l"(&g_done) : "memory");
            if (v < PREP_CTAS) __nanosleep(128);
        } while (v < PREP_CTAS);
    }
    __syncthreads();

    // ── payload: PLAIN loads (coherent via L2; never nc/invariant) ───────────
    const float4 hi0 = hiP[0];
    const float4 hi1 = hiP[32];
    const float4 sb0 = sbP[0];
    const float4 sb1 = sbP[32];

    float4 r0, r1;
    r0.x = hi0.x * inv - sb0.x * fs;  r0.y = hi0.y * inv - sb0.y * fs;
    r0.z = hi0.z * inv - sb0.z * fs;  r0.w = hi0.w * inv - sb0.w * fs;
    r1.x = hi1.x * inv - sb1.x * fs;  r1.y = hi1.y * inv - sb1.y * fs;
    r1.z = hi1.z * inv - sb1.z * fs;  r1.w = hi1.w * inv - sb1.w * fs;

    if (cross) {   // warp-uniform; ~47% of spans; T hot in L1/L2 (1 MB).
        const float4 t0 = tP[0];
        const float4 t1 = tP[32];
        r0.x += t0.x * inv;  r0.y += t0.y * inv;
        r0.z += t0.z * inv;  r0.w += t0.w * inv;
        r1.x += t1.x * inv;  r1.y += t1.y * inv;
        r1.z += t1.z * inv;  r1.w += t1.w * inv;
    }

    float4* __restrict__ o = out4 + (size_t)span * SLOTS + lane;
    o[0]  = r0;
    o[32] = r1;

    // ── last span CTA resets counters for the next graph replay ──────────────
    __syncthreads();
    if (threadIdx.x == 0) {
        const int old = atomicAdd(&g_fin, 1);
        if (old == SPAN_CTAS - 1) {
            g_done = 0;
            g_fin  = 0;
            __threadfence();
        }
    }
}

extern "C" void kernel_launch(void* const* d_in, const int* in_sizes, int n_in,
                              void* d_out, int out_size)
{
    const float4* seq4  = (const float4*)d_in[0];  // sequence_tensor [B,S,D] f32
    const int2*   spans = (const int2*)  d_in[1];  // span_indices    [B,N,2] i32
    float4*       out4  = (float4*)d_out;          // [B,N,D] f32

    fused_kernel<<<PREP_CTAS + SPAN_CTAS, 256>>>(seq4, spans, out4);
}

// round 14
// speedup vs baseline: 1.2918x; 1.2918x over previous
#include <cuda_runtime.h>
#include <cstdint>

#define B_     8
#define S_     2048
#define N_     4096
#define D_     256
#define SLOTS  (D_ / 4)      // 64 float4 per row
#define BLK    16            // >= max span extent (width <= 15 -> <= 16 rows)
#define NBLK   (S_ / BLK)    // 128

// Scratch (fp32): block-local inclusive prefix P (16.8 MB) + block totals T (1 MB).
// Span sum over rows [low, end]:
//   sum = P[end] + (cross ? T[blkE-1] : 0) - (haveSub ? P[low-1] : 0)
// cross = blk(low) != blk(end); cross => haveSub (width <= 15).
__device__ float g_P[(size_t)B_ * S_ * D_];
__device__ float g_T[(size_t)B_ * NBLK * D_];

// ── K1: streaming block-local prefix + total (measured ~3.5 us) ──────────────
// thread = (b, blk, slot); 65536 threads, 512 CTAs of 128.
__global__ __launch_bounds__(128) void k_prep(const float4* __restrict__ seq4)
{
    const int tid  = blockIdx.x * 128 + threadIdx.x;
    const int slot = tid & (SLOTS - 1);
    const int p    = tid >> 6;                  // (b, blk)
    const int blk  = p & (NBLK - 1);
    const int b    = p >> 7;                    // NBLK = 128

    const size_t base = ((size_t)b * S_ + (size_t)blk * BLK) * SLOTS + slot;
    const float4* __restrict__ q  = seq4 + base;
    float4* __restrict__        Pp = reinterpret_cast<float4*>(g_P) + base;

    float4 s = make_float4(0.f, 0.f, 0.f, 0.f);
#pragma unroll
    for (int r = 0; r < BLK; ++r) {
        const float4 v = __ldg(q + r * SLOTS);
        s.x += v.x; s.y += v.y; s.z += v.z; s.w += v.w;
        Pp[r * SLOTS] = s;                       // streaming store
    }
    reinterpret_cast<float4*>(g_T)[((size_t)b * NBLK + blk) * SLOTS + slot] = s;

#if __CUDA_ARCH__ >= 900
    cudaTriggerProgrammaticLaunchCompletion();   // let spans launch ASAP
#endif
}

// ── K2: spans — warp per span (measured 11.1 us); PDL-overlapped prologue ────
// blockDim 256 -> 8 spans per block, grid = 4096.
__global__ __launch_bounds__(256) void k_spans(
    const int2* __restrict__ spans,     // [B, N]
    float4*     __restrict__ out4)      // [B, N, D/4]
{
    const int span = blockIdx.x * 8 + (threadIdx.x >> 5);
    const int lane = threadIdx.x & 31;
    const int b    = span >> 12;                 // N_ = 4096

    // Prologue: metadata + all addressing BEFORE the dependency sync.
    const int2 se  = __ldg(&spans[span]);        // input, not produced by prep
    const int end  = se.y;
    const int m    = min(end - se.x, end);       // mask(w) <=> w <= m
    const int low  = end - m;                    // rows [low, end], count m+1

    const bool haveSub = (low & (BLK - 1)) != 0;
    const bool cross   = (low >> 4) != (end >> 4);   // => haveSub, blkE >= 1
    const int  selRow  = max(low - 1, 0);

    const float4* hiP = reinterpret_cast<const float4*>(g_P)
                      + (size_t)b * S_ * SLOTS + (size_t)end    * SLOTS + lane;
    const float4* sbP = reinterpret_cast<const float4*>(g_P)
                      + (size_t)b * S_ * SLOTS + (size_t)selRow * SLOTS + lane;
    const float4* tP  = reinterpret_cast<const float4*>(g_T)
                      + ((size_t)b * NBLK + max((end >> 4) - 1, 0)) * SLOTS + lane;

    const float inv = 1.0f / fmaxf((float)(m + 1), 1e-13f);
    const float fs  = haveSub ? inv : 0.0f;

#if __CUDA_ARCH__ >= 900
    cudaGridDependencySynchronize();             // wait for k_prep completion
#endif

    // Payload: PLAIN loads (coherent; not invariant -> cannot hoist above sync).
    const float4 hi0 = hiP[0];
    const float4 hi1 = hiP[32];
    const float4 sb0 = sbP[0];
    const float4 sb1 = sbP[32];

    float4 r0, r1;
    r0.x = hi0.x * inv - sb0.x * fs;  r0.y = hi0.y * inv - sb0.y * fs;
    r0.z = hi0.z * inv - sb0.z * fs;  r0.w = hi0.w * inv - sb0.w * fs;
    r1.x = hi1.x * inv - sb1.x * fs;  r1.y = hi1.y * inv - sb1.y * fs;
    r1.z = hi1.z * inv - sb1.z * fs;  r1.w = hi1.w * inv - sb1.w * fs;

    if (cross) {   // warp-uniform; ~47% of spans; T hot in L1/L2 (1 MB).
        const float4 t0 = tP[0];
        const float4 t1 = tP[32];
        r0.x += t0.x * inv;  r0.y += t0.y * inv;
        r0.z += t0.z * inv;  r0.w += t0.w * inv;
        r1.x += t1.x * inv;  r1.y += t1.y * inv;
        r1.z += t1.z * inv;  r1.w += t1.w * inv;
    }

    float4* __restrict__ o = out4 + (size_t)span * SLOTS + lane;
    o[0]  = r0;
    o[32] = r1;
}

extern "C" void kernel_launch(void* const* d_in, const int* in_sizes, int n_in,
                              void* d_out, int out_size)
{
    const float4* seq4  = (const float4*)d_in[0];  // sequence_tensor [B,S,D] f32
    const int2*   spans = (const int2*)  d_in[1];  // span_indices    [B,N,2] i32
    float4*       out4  = (float4*)d_out;          // [B,N,D] f32

    k_prep<<<(B_ * NBLK * SLOTS) / 128, 128>>>(seq4);

    // Spans with programmatic dependent launch: overlaps its launch + prologue
    // with k_prep's tail; cudaGridDependencySynchronize() gates the P/T reads.
    cudaLaunchConfig_t cfg = {};
    cfg.gridDim  = dim3((B_ * N_) / 8, 1, 1);
    cfg.blockDim = dim3(256, 1, 1);
    cfg.dynamicSmemBytes = 0;
    cfg.stream = 0;
    cudaLaunchAttribute attr[1];
    attr[0].id = cudaLaunchAttributeProgrammaticStreamSerialization;
    attr[0].val.programmaticStreamSerializationAllowed = 1;
    cfg.attrs = attr;
    cfg.numAttrs = 1;
    cudaLaunchKernelEx(&cfg, k_spans, spans, out4);
}